// round 3
// baseline (speedup 1.0000x reference)
#include <cuda_runtime.h>

#define VOCABN 101
#define EMBN   32
#define HIDN   32
#define TT     512
#define NB     4096
#define NGATE  128
#define SPW    4     // sequences per warp
#define WPB    2     // warps per CTA  -> CTA = 64 threads, 512 CTAs

typedef unsigned long long ull;

// ---------------- packed f32x2 helpers (Blackwell) ----------------
__device__ __forceinline__ ull pack2(float lo, float hi) {
    ull r;
    asm("mov.b64 %0, {%1, %2};" : "=l"(r) : "f"(lo), "f"(hi));
    return r;
}
__device__ __forceinline__ void unpack2(ull v, float& lo, float& hi) {
    asm("mov.b64 {%0, %1}, %2;" : "=f"(lo), "=f"(hi) : "l"(v));
}
__device__ __forceinline__ void fma2(ull& acc, ull a, ull b) {
    asm("fma.rn.f32x2 %0, %1, %2, %0;" : "+l"(acc) : "l"(a), "l"(b));
}

// ---------------- fast transcendentals (MUFU ex2 + rcp) ----------------
__device__ __forceinline__ float ex2f(float x) {
    float r; asm("ex2.approx.f32 %0, %1;" : "=f"(r) : "f"(x)); return r;
}
__device__ __forceinline__ float rcpf(float x) {
    float r; asm("rcp.approx.f32 %0, %1;" : "=f"(r) : "f"(x)); return r;
}
__device__ __forceinline__ float sigmoidf_fast(float x) {
    return rcpf(1.0f + ex2f(-1.4426950408889634f * x));
}
__device__ __forceinline__ float tanhf_fast(float x) {
    float s = rcpf(1.0f + ex2f(-2.8853900817779268f * x));
    return fmaf(2.0f, s, -1.0f);
}

// ---------------- precomputed scratch (device globals) ----------------
// gate pre-activation table: table[v] = emb[v] @ Wx + b, packed pairs
__device__ ull g_tabIF[VOCABN][32];
__device__ ull g_tabGO[VOCABN][32];
// Wh in paired layout: WhIF[j][l] = (Wh[j][l], Wh[j][l+32]), etc.
__device__ ull g_WhIF[32][32];
__device__ ull g_WhGO[32][32];

// ---------------- prep kernel ----------------
__global__ void prep_kernel(const float* __restrict__ emb,
                            const float* __restrict__ Wx,
                            const float* __restrict__ Wh,
                            const float* __restrict__ bias) {
    int l = threadIdx.x;
    int v = blockIdx.x;
    if (v < VOCABN) {
        float a0 = 0.f, a1 = 0.f, a2 = 0.f, a3 = 0.f;
#pragma unroll
        for (int e = 0; e < EMBN; e++) {
            float xe = emb[v * EMBN + e];
            const float* w = Wx + e * NGATE;
            a0 = fmaf(xe, w[l],      a0);
            a1 = fmaf(xe, w[l + 32], a1);
            a2 = fmaf(xe, w[l + 64], a2);
            a3 = fmaf(xe, w[l + 96], a3);
        }
        a0 += bias[l];      a1 += bias[l + 32];
        a2 += bias[l + 64]; a3 += bias[l + 96];
        g_tabIF[v][l] = pack2(a0, a1);
        g_tabGO[v][l] = pack2(a2, a3);
    }
    if (v < 32) {
        int j = v;
        g_WhIF[j][l] = pack2(Wh[j * NGATE + l],      Wh[j * NGATE + l + 32]);
        g_WhGO[j][l] = pack2(Wh[j * NGATE + l + 64], Wh[j * NGATE + l + 96]);
    }
}

// ---------------- main LSTM kernel: 4 sequences per warp ----------------
__global__ void __launch_bounds__(WPB * 32, 4)
lstm_kernel(const int* __restrict__ x,
            const float* __restrict__ W_fc,
            const float* __restrict__ b_fc,
            float* __restrict__ out) {
    // double-buffered per-warp, per-seq h staged as duplicated pairs (h_j, h_j)
    __shared__ __align__(16) ull hdup[2][WPB][SPW][HIDN];

    const int warp = threadIdx.x >> 5;
    const int lane = threadIdx.x & 31;
    const int b0   = (blockIdx.x * WPB + warp) * SPW;

    // Wh register-resident in paired layout (shared by all 4 sequences)
    ull wIF[32], wGO[32];
#pragma unroll
    for (int j = 0; j < 32; j++) {
        wIF[j] = g_WhIF[j][lane];
        wGO[j] = g_WhGO[j][lane];
    }

    float c[SPW], h[SPW];
#pragma unroll
    for (int s = 0; s < SPW; s++) {
        c[s] = 0.f; h[s] = 0.f;
        hdup[0][warp][s][lane] = 0ull;
    }
    __syncwarp();

    const int* xb = x + (long long)b0 * TT;
    int p = 0;

    for (int tb = 0; tb < TT; tb += 32) {
        int xv[SPW];
#pragma unroll
        for (int s = 0; s < SPW; s++)
            xv[s] = xb[s * TT + tb + lane];   // coalesced per sequence

#pragma unroll 1
        for (int ss = 0; ss < 32; ss++) {
            // seed accumulators from precomputed input-gate table
            ull aIF[SPW], aGO[SPW];
#pragma unroll
            for (int s = 0; s < SPW; s++) {
                int v = __shfl_sync(0xffffffffu, xv[s], ss);
                aIF[s] = g_tabIF[v][lane];
                aGO[s] = g_tabGO[v][lane];
            }

            // interleaved matvec: 4 independent chains hide each other's latency
#pragma unroll
            for (int k = 0; k < 16; k++) {
#pragma unroll
                for (int s = 0; s < SPW; s++) {
                    ulonglong2 hv = ((const ulonglong2*)hdup[p][warp][s])[k];
                    fma2(aIF[s], hv.x, wIF[2 * k]);
                    fma2(aIF[s], hv.y, wIF[2 * k + 1]);
                    fma2(aGO[s], hv.x, wGO[2 * k]);
                    fma2(aGO[s], hv.y, wGO[2 * k + 1]);
                }
            }

            // activations: 4 MUFU chains overlap across sequences
#pragma unroll
            for (int s = 0; s < SPW; s++) {
                float zi, zf, zg, zo;
                unpack2(aIF[s], zi, zf);
                unpack2(aGO[s], zg, zo);

                float is = sigmoidf_fast(zi);
                float fs = sigmoidf_fast(zf);
                float gt = tanhf_fast(zg);
                float os = sigmoidf_fast(zo);

                c[s] = fmaf(fs, c[s], is * gt);
                h[s] = os * tanhf_fast(c[s]);

                hdup[p ^ 1][warp][s][lane] = pack2(h[s], h[s]);
            }
            __syncwarp();      // new h visible; old buffer's reads all complete
            p ^= 1;
        }
    }

    // final FC: out[b] = h @ W_fc + b_fc   (W_fc is [32,2] row-major)
    float wf0 = W_fc[2 * lane];
    float wf1 = W_fc[2 * lane + 1];
#pragma unroll
    for (int s = 0; s < SPW; s++) {
        float p0 = h[s] * wf0;
        float p1 = h[s] * wf1;
#pragma unroll
        for (int off = 16; off; off >>= 1) {
            p0 += __shfl_xor_sync(0xffffffffu, p0, off);
            p1 += __shfl_xor_sync(0xffffffffu, p1, off);
        }
        if (lane == 0) {
            out[2 * (b0 + s)]     = p0 + b_fc[0];
            out[2 * (b0 + s) + 1] = p1 + b_fc[1];
        }
    }
}

extern "C" void kernel_launch(void* const* d_in, const int* in_sizes, int n_in,
                              void* d_out, int out_size) {
    const int*   x    = (const int*)  d_in[0];
    const float* emb  = (const float*)d_in[1];
    const float* Wx   = (const float*)d_in[2];
    const float* Wh   = (const float*)d_in[3];
    const float* bias = (const float*)d_in[4];
    const float* W_fc = (const float*)d_in[5];
    const float* b_fc = (const float*)d_in[6];
    float* out = (float*)d_out;

    prep_kernel<<<VOCABN, 32>>>(emb, Wx, Wh, bias);
    lstm_kernel<<<NB / (SPW * WPB), WPB * 32>>>(x, W_fc, b_fc, out);
}

// round 4
// speedup vs baseline: 1.3047x; 1.3047x over previous
#include <cuda_runtime.h>

#define VOCABN 101
#define EMBN   32
#define HIDN   32
#define TT     512
#define NB     4096
#define NGATE  128
#define WPB    4     // warps (sequences) per CTA

typedef unsigned long long ull;

// ---------------- packed f32x2 helpers (Blackwell) ----------------
__device__ __forceinline__ ull pack2(float lo, float hi) {
    ull r;
    asm("mov.b64 %0, {%1, %2};" : "=l"(r) : "f"(lo), "f"(hi));
    return r;
}
__device__ __forceinline__ void unpack2(ull v, float& lo, float& hi) {
    asm("mov.b64 {%0, %1}, %2;" : "=f"(lo), "=f"(hi) : "l"(v));
}
__device__ __forceinline__ void fma2(ull& acc, ull a, ull b) {
    asm("fma.rn.f32x2 %0, %1, %2, %0;" : "+l"(acc) : "l"(a), "l"(b));
}
__device__ __forceinline__ void add2(ull& a, ull b) {
    asm("add.rn.f32x2 %0, %0, %1;" : "+l"(a) : "l"(b));
}

// ---------------- HW tanh (single MUFU op, sm_75+) ----------------
__device__ __forceinline__ float tanh_hw(float x) {
    float r; asm("tanh.approx.f32 %0, %1;" : "=f"(r) : "f"(x)); return r;
}
// sigmoid(z) = 0.5*tanh(z/2) + 0.5 ; the z/2 scaling is baked into the
// precomputed table and Wh for gates i,f,o, so here it's tanh + one FFMA.
__device__ __forceinline__ float sig_from_half(float z_half) {
    return fmaf(0.5f, tanh_hw(z_half), 0.5f);
}

// ---------------- precomputed scratch (device globals) ----------------
// tabIF[v][l] = (0.5*zi, 0.5*zf) pre-activation pair (scaled for sigmoid)
// tabGO[v][l] = (zg, 0.5*zo)     (g unscaled for tanh, o scaled for sigmoid)
__device__ ull g_tabIF[VOCABN][32];
__device__ ull g_tabGO[VOCABN][32];
// Wh with matching per-element scaling baked in
__device__ ull g_WhIF[32][32];
__device__ ull g_WhGO[32][32];

// ---------------- prep kernel ----------------
__global__ void prep_kernel(const float* __restrict__ emb,
                            const float* __restrict__ Wx,
                            const float* __restrict__ Wh,
                            const float* __restrict__ bias) {
    int l = threadIdx.x;   // 0..31
    int v = blockIdx.x;
    if (v < VOCABN) {
        float a0 = 0.f, a1 = 0.f, a2 = 0.f, a3 = 0.f;
#pragma unroll
        for (int e = 0; e < EMBN; e++) {
            float xe = emb[v * EMBN + e];
            const float* w = Wx + e * NGATE;
            a0 = fmaf(xe, w[l],      a0);
            a1 = fmaf(xe, w[l + 32], a1);
            a2 = fmaf(xe, w[l + 64], a2);
            a3 = fmaf(xe, w[l + 96], a3);
        }
        a0 += bias[l];      a1 += bias[l + 32];
        a2 += bias[l + 64]; a3 += bias[l + 96];
        // bake sigmoid's z/2 into i, f, o
        g_tabIF[v][l] = pack2(0.5f * a0, 0.5f * a1);
        g_tabGO[v][l] = pack2(a2, 0.5f * a3);
    }
    if (v < 32) {
        int j = v;
        g_WhIF[j][l] = pack2(0.5f * Wh[j * NGATE + l],
                             0.5f * Wh[j * NGATE + l + 32]);
        g_WhGO[j][l] = pack2(Wh[j * NGATE + l + 64],
                             0.5f * Wh[j * NGATE + l + 96]);
    }
}

// ---------------- main LSTM kernel: one warp per sequence ----------------
__global__ void __launch_bounds__(WPB * 32, 3)
lstm_kernel(const int* __restrict__ x,
            const float* __restrict__ W_fc,
            const float* __restrict__ b_fc,
            float* __restrict__ out) {
    // double-buffered per-warp h staged as duplicated pairs (h_j, h_j):
    // one LDS.128 delivers two FMA-ready packed operands
    __shared__ __align__(16) ull hdup[2][WPB][HIDN];

    const int warp = threadIdx.x >> 5;
    const int lane = threadIdx.x & 31;
    const int b    = blockIdx.x * WPB + warp;

    // Wh register-resident in paired layout (reused 512 times)
    ull wIF[32], wGO[32];
#pragma unroll
    for (int j = 0; j < 32; j++) {
        wIF[j] = g_WhIF[j][lane];
        wGO[j] = g_WhGO[j][lane];
    }

    hdup[0][warp][lane] = 0ull;
    float c = 0.f, h = 0.f;
    __syncwarp();

    const int* xb = x + b * TT;
    int p = 0;

    for (int tb = 0; tb < TT; tb += 32) {
        int xv = xb[tb + lane];       // coalesced: 32 timesteps staged per lane
#pragma unroll 4
        for (int ss = 0; ss < 32; ss++) {
            int v = __shfl_sync(0xffffffffu, xv, ss);

            // 4 independent chains per gate-pair (depth 8 each);
            // table LDG seeds only chain 0 -> its latency hides behind 1..3
            ull aIF[4], aGO[4];
            aIF[0] = g_tabIF[v][lane];
            aGO[0] = g_tabGO[v][lane];
            aIF[1] = aIF[2] = aIF[3] = 0ull;
            aGO[1] = aGO[2] = aGO[3] = 0ull;

            const ulonglong2* h2 = (const ulonglong2*)hdup[p][warp];
#pragma unroll
            for (int k = 0; k < 16; k++) {
                ulonglong2 hv = h2[k];       // broadcast LDS.128
                const int c0 = (2 * k) & 3;
                const int c1 = (2 * k + 1) & 3;
                fma2(aIF[c0], hv.x, wIF[2 * k]);
                fma2(aGO[c0], hv.x, wGO[2 * k]);
                fma2(aIF[c1], hv.y, wIF[2 * k + 1]);
                fma2(aGO[c1], hv.y, wGO[2 * k + 1]);
            }
            add2(aIF[0], aIF[1]); add2(aIF[2], aIF[3]); add2(aIF[0], aIF[2]);
            add2(aGO[0], aGO[1]); add2(aGO[2], aGO[3]); add2(aGO[0], aGO[2]);

            float zi2, zf2, zg, zo2;
            unpack2(aIF[0], zi2, zf2);
            unpack2(aGO[0], zg, zo2);

            float is = sig_from_half(zi2);
            float fs = sig_from_half(zf2);
            float os = sig_from_half(zo2);
            float gt = tanh_hw(zg);

            c = fmaf(fs, c, is * gt);
            h = os * tanh_hw(c);

            hdup[p ^ 1][warp][lane] = pack2(h, h);
            __syncwarp();                 // new h visible; old buffer untouched
            p ^= 1;
        }
    }

    // final FC: out[b] = h @ W_fc + b_fc   (W_fc is [32,2] row-major)
    float p0 = h * W_fc[2 * lane];
    float p1 = h * W_fc[2 * lane + 1];
#pragma unroll
    for (int off = 16; off; off >>= 1) {
        p0 += __shfl_xor_sync(0xffffffffu, p0, off);
        p1 += __shfl_xor_sync(0xffffffffu, p1, off);
    }
    if (lane == 0) {
        out[2 * b]     = p0 + b_fc[0];
        out[2 * b + 1] = p1 + b_fc[1];
    }
}

extern "C" void kernel_launch(void* const* d_in, const int* in_sizes, int n_in,
                              void* d_out, int out_size) {
    const int*   x    = (const int*)  d_in[0];
    const float* emb  = (const float*)d_in[1];
    const float* Wx   = (const float*)d_in[2];
    const float* Wh   = (const float*)d_in[3];
    const float* bias = (const float*)d_in[4];
    const float* W_fc = (const float*)d_in[5];
    const float* b_fc = (const float*)d_in[6];
    float* out = (float*)d_out;

    prep_kernel<<<VOCABN, 32>>>(emb, Wx, Wh, bias);
    lstm_kernel<<<NB / WPB, WPB * 32>>>(x, W_fc, b_fc, out);
}